// round 14
// baseline (speedup 1.0000x reference)
#include <cuda_runtime.h>
#include <cstdint>

#define NB 16
#define CI 64
#define CO 64
#define HH 128
#define WW 128
#define TH 8
#define TW 32
#define NTHREADS 256
#define NCHUNK 8                    // 8 channels per chunk (k32)

// staged x tile: per channel 10 rows x 40 floats ([w0-4, w0+36))
#define XROW 40
#define XS_CH (10*XROW)             // 400 floats
#define XS_CHUNK (8*XS_CH)          // 3200 floats per chunk
#define NSEG (8*10*10)              // 800 16B segments per chunk

// smem byte offsets (GEMM bases 128B-aligned)
#define XB_OFF 0                    // 3 bufs * 12800B = 38400
#define WH_OFF 38400                // W fp16: 16 k16-blocks * 64o * 32B = 32768
#define AH_OFF (WH_OFF+32768)       // 71168: A fp16, 2 chunk-bufs * 16384
#define SMEM_BYTES (AH_OFF+32768)   // 103936 -> 2 CTAs/SM

// W layout swizzle (unchanged): k-major 32B rows, 16B-unit XOR
#define SWZ(row, half) (((((row)*2+(half)) ^ (((row)>>2)&1)))*16)
// A layout: 16B unit u = 2*pix+half, swizzled u^((pix>>2)&7)
#define ASWZ_U(pix, half) (((uint32_t)(2*(pix)+(half))) ^ ((uint32_t)(((pix)>>2)&7)))

// pack two f32 -> f16x2 (lo = a, hi = b), rn-even
__device__ __forceinline__ uint32_t pf16(float a, float b){
    uint32_t pk;
    asm("cvt.rn.f16x2.f32 %0, %1, %2;" : "=r"(pk) : "f"(b), "f"(a));
    return pk;
}
__device__ __forceinline__ void ldm4(uint32_t* r, uint32_t addr){
    asm volatile("ldmatrix.sync.aligned.m8n8.x4.shared.b16 {%0,%1,%2,%3}, [%4];"
                 : "=r"(r[0]), "=r"(r[1]), "=r"(r[2]), "=r"(r[3]) : "r"(addr));
}
__device__ __forceinline__ void mma16816(float* d, const uint32_t* a, uint32_t b0, uint32_t b1){
    asm volatile("mma.sync.aligned.m16n8k16.row.col.f32.f16.f16.f32 "
                 "{%0,%1,%2,%3}, {%4,%5,%6,%7}, {%8,%9}, {%0,%1,%2,%3};"
                 : "+f"(d[0]), "+f"(d[1]), "+f"(d[2]), "+f"(d[3])
                 : "r"(a[0]), "r"(a[1]), "r"(a[2]), "r"(a[3]), "r"(b0), "r"(b1));
}

// vectorized 16B x loader with hoisted addressing: soff<0 marks OOB (zero-fill)
__device__ __forceinline__ void load_chunk_vec(const float* __restrict__ xb, int ch, int buf,
                                               int tid, unsigned sb, const int* soff){
    unsigned dbase = sb + (unsigned)XB_OFF + (unsigned)buf*(XS_CHUNK*4u);
    const float* xc = xb + (size_t)(ch*8) * (HH*WW);
    #pragma unroll
    for (int k = 0; k < 4; k++){
        int e = tid + k*256;
        if (k < 3 || tid < (NSEG - 3*256)){
            int so = soff[k];
            const float* src = (so >= 0) ? (xc + so) : xb;
            int sz = (so >= 0) ? 16 : 0;
            asm volatile("cp.async.cg.shared.global [%0], [%1], 16, %2;"
                         :: "r"(dbase + (unsigned)e*16u), "l"(src), "r"(sz));
        }
    }
}

// build A chunk: lane (lp,lq) builds pixels 4lp..4lp+3 (warp row) x channels 2lq,2lq+1
__device__ __forceinline__ void build_A(char* smA, const float* xsb,
                                        int warp, int lp, int lq,
                                        const float* c1v, const float* s1v)
{
    const float Qc = 0.35355339059327376220f;
    uint32_t keep[8];                    // cg=0 results: 4 pixels x {hu0,hu1}
    #pragma unroll
    for (int cg = 0; cg < 2; cg++){
        const float* bp = xsb + (2*lq + cg)*XS_CH + warp*XROW + 4*lp;
        float4 a0 = *(const float4*)(bp);
        float4 a1 = *(const float4*)(bp + 4);
        float4 a2 = *(const float4*)(bp + 8);
        float4 b0 = *(const float4*)(bp + XROW);
        float4 b1 = *(const float4*)(bp + XROW + 4);
        float4 b2 = *(const float4*)(bp + XROW + 8);
        float4 d0 = *(const float4*)(bp + 2*XROW);
        float4 d1 = *(const float4*)(bp + 2*XROW + 4);
        float4 d2 = *(const float4*)(bp + 2*XROW + 8);
        float r0[12] = {a0.x,a0.y,a0.z,a0.w, a1.x,a1.y,a1.z,a1.w, a2.x,a2.y,a2.z,a2.w};
        float r1[12] = {b0.x,b0.y,b0.z,b0.w, b1.x,b1.y,b1.z,b1.w, b2.x,b2.y,b2.z,b2.w};
        float r2[12] = {d0.x,d0.y,d0.z,d0.w, d1.x,d1.y,d1.z,d1.w, d2.x,d2.y,d2.z,d2.w};
        #pragma unroll
        for (int i = 0; i < 4; i++){
            float t0=r0[3+i], t1=r0[4+i], t2=r0[5+i];
            float t3=r1[3+i], t4=r1[4+i], t5=r1[5+i];
            float t6=r2[3+i], t7=r2[4+i], t8=r2[5+i];
            float c1 = c1v[i], s1 = s1v[i];
            float c2 = 2.f*c1*c1 - 1.f, s2 = 2.f*s1*c1;
            float cps = c1 + s1, cms = c1 - s1;
            float ring = ((t0+t1)+(t2+t3)) + ((t5+t6)+(t7+t8));
            float z2 = Qc*(cps*(t8-t0) + cms*(t2-t6)) + 0.5f*(c1*(t5-t3) + s1*(t7-t1));
            float z3 = 0.5f*(s2*((t0+t8)-(t2+t6)) + c2*((t3+t5)-(t1+t7)));
            uint32_t h0u = pf16(t4, Qc*ring);
            uint32_t h1u = pf16(z2, z3);
            if (cg == 0){
                keep[i*2]   = h0u;
                keep[i*2+1] = h1u;
            } else {
                int pix = warp*32 + 4*lp + i;
                uint32_t u = ASWZ_U(pix, lq & 1);
                char* dst = smA + (lq >> 1)*8192 + u*16u;
                *(uint4*)dst = make_uint4(keep[i*2], keep[i*2+1], h0u, h1u);
            }
        }
    }
}

__global__ __launch_bounds__(NTHREADS, 2)
void steered_mma(const float* __restrict__ x, const float* __restrict__ theta,
                 const float* __restrict__ wts, const float* __restrict__ bias,
                 float* __restrict__ out)
{
    extern __shared__ float smf[];
    char* sm = (char*)smf;
    const unsigned sb = (unsigned)__cvta_generic_to_shared(sm);
    const int tid = threadIdx.x;
    const int lane = tid & 31, warp = tid >> 5;
    const int lp = lane & 7, lq = lane >> 3;
    const int n = blockIdx.z, h0 = blockIdx.y*TH, w0 = blockIdx.x*TW;
    const float* xb = x + (size_t)n*CI*HH*WW;

    // ---- hoisted per-thread 16B-segment addressing (chunk-invariant) ----
    int soff[4];
    #pragma unroll
    for (int k = 0; k < 4; k++){
        int e = tid + k*256;
        int j = e / 100; int rem = e - j*100;
        int r = rem / 10;  int s = rem - r*10;
        int gh = h0 - 1 + r;
        int gw = w0 - 4 + s*4;
        bool v = (e < NSEG) && ((unsigned)gh < (unsigned)HH) && ((unsigned)gw < (unsigned)WW);
        soff[k] = v ? (j*(HH*WW) + gh*WW + gw) : -1;
    }

    // prefetch x chunks 0,1 into bufs 0,1
    load_chunk_vec(xb, 0, 0, tid, sb, soff);
    asm volatile("cp.async.commit_group;" ::: "memory");
    load_chunk_vec(xb, 1, 1, tid, sb, soff);
    asm volatile("cp.async.commit_group;" ::: "memory");

    // ---- W preprocessing: wts[o][i][4] -> W[k16-block][o][k16] fp16, swizzled ----
    #pragma unroll 4
    for (int t = 0; t < 16; t++){
        int e = tid + t*256;
        int o = e & 63, i = e >> 6;
        float4 v = ((const float4*)wts)[o*64 + i];     // w[o][i][0..3]
        int cc = i >> 2, j = i & 3;
        uint32_t h0u = pf16(v.x, v.y);
        uint32_t h1u = pf16(v.z, v.w);
        int off = cc*2048 + SWZ(o, (j>>1)) + (j&1)*8;
        *(uint2*)(sm + WH_OFF + off) = make_uint2(h0u, h1u);
    }

    // ---- per-pixel harmonics for this lane's 4 build pixels (row h0+warp) ----
    float c1v[4], s1v[4];
    {
        float4 tv = *(const float4*)(theta + ((size_t)n*HH + (h0 + warp))*WW + (w0 + 4*lp));
        const float TP = 6.28318530717958647692f;
        sincosf(TP*tv.x, &s1v[0], &c1v[0]);
        sincosf(TP*tv.y, &s1v[1], &c1v[1]);
        sincosf(TP*tv.z, &s1v[2], &c1v[2]);
        sincosf(TP*tv.w, &s1v[3], &c1v[3]);
    }

    // ---- per-lane ldmatrix addresses ----
    uint32_t aswz0, aswz1;
    {
        int pl = lane & 15, half = lane >> 4;
        aswz0 = ASWZ_U(warp*32 + pl,      half) * 16u;
        aswz1 = ASWZ_U(warp*32 + 16 + pl, half) * 16u;
        // note: ((pix>>2)&7) uses pix local bits only since warp*32>>2 is mult of 8
    }
    const int olc = (lane & 7) + ((lane >> 4) << 3);
    const int whalf = (lane >> 3) & 1;
    uint32_t wswz[4];
    #pragma unroll
    for (int np = 0; np < 4; np++) wswz[np] = SWZ(np*16 + olc, whalf);

    float acc[2][8][4];
    #pragma unroll
    for (int a = 0; a < 2; a++)
        #pragma unroll
        for (int b = 0; b < 8; b++)
            #pragma unroll
            for (int q = 0; q < 4; q++) acc[a][b][q] = 0.f;

    // ---- pipeline prologue: X(0) ready -> build A(0) into buf 0 ----
    asm volatile("cp.async.wait_group 1;" ::: "memory");   // X(0) complete
    __syncthreads();                                       // X(0) visible CTA-wide
    build_A(sm + AH_OFF, smf + 0*XS_CHUNK, warp, lp, lq, c1v, s1v);
    load_chunk_vec(xb, 2, 2, tid, sb, soff);               // prefetch X(2) -> buf 2
    asm volatile("cp.async.commit_group;" ::: "memory");

    for (int c = 0; c < NCHUNK; c++){
        __syncwarp();            // A(c) STS (warp-private rows) -> ldmatrix visibility

        const unsigned abuf = sb + AH_OFF + (unsigned)(c & 1)*16384u;
        uint32_t ahf0[2][4];     // kk=0 fragments, loaded before the overlapped build
        ldm4(ahf0[0], abuf + aswz0);
        ldm4(ahf0[1], abuf + aswz1);

        if (c < NCHUNK-1){
            if (c < NCHUNK-2) asm volatile("cp.async.wait_group 1;" ::: "memory");
            else              asm volatile("cp.async.wait_group 0;" ::: "memory");
            __syncthreads();     // X(c+1) visible; all reads of X-buf c%3 retired
            if (c + 3 < NCHUNK){
                int wb = c % 3;  // (c+3)%3
                load_chunk_vec(xb, c+3, wb, tid, sb, soff);
                asm volatile("cp.async.commit_group;" ::: "memory");
            }
            build_A(sm + AH_OFF + ((c+1)&1)*16384, smf + ((c+1)%3)*XS_CHUNK,
                    warp, lp, lq, c1v, s1v);
        }

        // ---- GEMM kk=0 ----
        {
            uint32_t wh_base = sb + WH_OFF + (unsigned)(2*c)*2048u;
            #pragma unroll
            for (int np = 0; np < 4; np++){
                uint32_t bh[4];
                ldm4(bh, wh_base + wswz[np]);
                #pragma unroll
                for (int s = 0; s < 2; s++){
                    #pragma unroll
                    for (int mt = 0; mt < 2; mt++)
                        mma16816(acc[mt][np*2 + s], ahf0[mt], bh[s*2], bh[s*2+1]);
                }
            }
        }
        // ---- GEMM kk=1 ----
        {
            uint32_t ahf1[2][4];
            ldm4(ahf1[0], abuf + 8192u + aswz0);
            ldm4(ahf1[1], abuf + 8192u + aswz1);
            uint32_t wh_base = sb + WH_OFF + (unsigned)(2*c + 1)*2048u;
            #pragma unroll
            for (int np = 0; np < 4; np++){
                uint32_t bh[4];
                ldm4(bh, wh_base + wswz[np]);
                #pragma unroll
                for (int s = 0; s < 2; s++){
                    #pragma unroll
                    for (int mt = 0; mt < 2; mt++)
                        mma16816(acc[mt][np*2 + s], ahf1[mt], bh[s*2], bh[s*2+1]);
                }
            }
        }
    }

    // ---- epilogue: bias + store ----
    const int gr = lane >> 2, tg = lane & 3;
    float* ob = out + (size_t)n*CO*HH*WW;
    #pragma unroll
    for (int mt = 0; mt < 2; mt++){
        size_t off0 = (size_t)(h0 + warp)*WW + (w0 + mt*16 + gr);
        size_t off1 = off0 + 8;
        #pragma unroll
        for (int nt = 0; nt < 8; nt++){
            int o = nt*8 + tg*2;
            float b0v = __ldg(bias + o);
            float b1v = __ldg(bias + o + 1);
            ob[(size_t)o*(HH*WW)     + off0] = acc[mt][nt][0] + b0v;
            ob[(size_t)(o+1)*(HH*WW) + off0] = acc[mt][nt][1] + b1v;
            ob[(size_t)o*(HH*WW)     + off1] = acc[mt][nt][2] + b0v;
            ob[(size_t)(o+1)*(HH*WW) + off1] = acc[mt][nt][3] + b1v;
        }
    }
}

extern "C" void kernel_launch(void* const* d_in, const int* in_sizes, int n_in,
                              void* d_out, int out_size) {
    const float* x     = (const float*)d_in[0];
    const float* theta = (const float*)d_in[1];
    const float* wts   = (const float*)d_in[2];
    const float* bias  = (const float*)d_in[3];
    float* out = (float*)d_out;

    cudaFuncSetAttribute(steered_mma,
                         cudaFuncAttributeMaxDynamicSharedMemorySize, SMEM_BYTES);
    dim3 grid(WW/TW, HH/TH, NB);
    steered_mma<<<grid, NTHREADS, SMEM_BYTES>>>(x, theta, wts, bias, out);
}

// round 15
// speedup vs baseline: 1.1868x; 1.1868x over previous
#include <cuda_runtime.h>
#include <cstdint>

#define NB 16
#define CI 64
#define CO 64
#define HH 128
#define WW 128
#define TH 8
#define TW 32
#define NTHREADS 256
#define NCHUNK 16                   // 4 channels per chunk (one k16 block)

#define XROW 40
// warp-private X: [warp][buf<3][ch<4][row3<3][40 floats]
#define XBUF_BYTES 1920             // 4*3*40*4
#define XW_WARP_BYTES (3*XBUF_BYTES)// 5760
#define XW_TOTAL (8*XW_WARP_BYTES)  // 46080
#define WH_OFF XW_TOTAL             // W fp16: 16 k16-blocks * 2048B = 32768
#define AH_OFF (WH_OFF+32768)       // 78848: A fp16, 2 chunk-bufs * 8192
#define SMEM_BYTES (AH_OFF+16384)   // 95232 -> 2 CTAs/SM

// k-major 32B rows; 16B-unit XOR swizzle -> conflict-free ldmatrix/STS
#define SWZ(row, half) (((((row)*2+(half)) ^ (((row)>>2)&1)))*16)

// pack two f32 -> f16x2 (lo = a, hi = b), rn-even
__device__ __forceinline__ uint32_t pf16(float a, float b){
    uint32_t pk;
    asm("cvt.rn.f16x2.f32 %0, %1, %2;" : "=r"(pk) : "f"(b), "f"(a));
    return pk;
}
__device__ __forceinline__ void ldm4(uint32_t* r, uint32_t addr){
    asm volatile("ldmatrix.sync.aligned.m8n8.x4.shared.b16 {%0,%1,%2,%3}, [%4];"
                 : "=r"(r[0]), "=r"(r[1]), "=r"(r[2]), "=r"(r[3]) : "r"(addr));
}
__device__ __forceinline__ void mma16816(float* d, const uint32_t* a, uint32_t b0, uint32_t b1){
    asm volatile("mma.sync.aligned.m16n8k16.row.col.f32.f16.f16.f32 "
                 "{%0,%1,%2,%3}, {%4,%5,%6,%7}, {%8,%9}, {%0,%1,%2,%3};"
                 : "+f"(d[0]), "+f"(d[1]), "+f"(d[2]), "+f"(d[3])
                 : "r"(a[0]), "r"(a[1]), "r"(a[2]), "r"(a[3]), "r"(b0), "r"(b1));
}

// warp-private 16B cp.async loader: lane covers 120 segs in 4 steps; soff<0 = OOB zero-fill
__device__ __forceinline__ void load_chunk_warp(const float* __restrict__ xb, int c, int buf,
                                                unsigned xwbase, int lane, const int* soff){
    unsigned dbase = xwbase + (unsigned)buf*XBUF_BYTES;
    const float* xc = xb + (size_t)(c*4) * (HH*WW);
    #pragma unroll
    for (int k = 0; k < 4; k++){
        if (k < 3 || lane < 24){
            int e = lane + k*32;
            int so = soff[k];
            const float* src = (so >= 0) ? (xc + so) : xb;
            int sz = (so >= 0) ? 16 : 0;
            asm volatile("cp.async.cg.shared.global [%0], [%1], 16, %2;"
                         :: "r"(dbase + (unsigned)e*16u), "l"(src), "r"(sz));
        }
    }
    asm volatile("cp.async.commit_group;" ::: "memory");
}

__global__ __launch_bounds__(NTHREADS, 2)
void steered_mma(const float* __restrict__ x, const float* __restrict__ theta,
                 const float* __restrict__ wts, const float* __restrict__ bias,
                 float* __restrict__ out)
{
    extern __shared__ float smf[];
    char* sm = (char*)smf;
    const unsigned sb = (unsigned)__cvta_generic_to_shared(sm);
    const int tid = threadIdx.x;
    const int lane = tid & 31, warp = tid >> 5;
    const int n = blockIdx.z, h0 = blockIdx.y*TH, w0 = blockIdx.x*TW;
    const float* xb = x + (size_t)n*CI*HH*WW;
    const unsigned xwbase = sb + (unsigned)warp*XW_WARP_BYTES;

    // ---- hoisted per-lane segment addressing (chunk-invariant, warp-private rows) ----
    // seg e = lane+32k (e<120): ch=e/30, r3=(e%30)/10, s=e%10
    // dst float off = 4e (contiguous); src = ch*HW + (h0+warp-1+r3)*WW + (w0-4+4s)
    int soff[4];
    #pragma unroll
    for (int k = 0; k < 4; k++){
        int e = lane + k*32;
        int ch = e / 30; int rem = e - ch*30;
        int r3 = rem / 10; int s = rem - r3*10;
        int gh = h0 + warp - 1 + r3;
        int gw = w0 - 4 + s*4;
        bool v = (e < 120) && ((unsigned)gh < (unsigned)HH) && ((unsigned)gw < (unsigned)WW);
        soff[k] = v ? (ch*(HH*WW) + gh*WW + gw) : -1;
    }

    // prologue: warp-private prefetch of chunks 0,1
    load_chunk_warp(xb, 0, 0, xwbase, lane, soff);
    load_chunk_warp(xb, 1, 1, xwbase, lane, soff);

    // ---- W preprocessing: wts[o][i][4] -> W[k16-block][o][k16] fp16, swizzled ----
    #pragma unroll 4
    for (int t = 0; t < 16; t++){
        int e = tid + t*256;
        int o = e & 63, i = e >> 6;
        float4 v = ((const float4*)wts)[o*64 + i];     // w[o][i][0..3]
        int cc = i >> 2, j = i & 3;
        uint32_t h0u = pf16(v.x, v.y);
        uint32_t h1u = pf16(v.z, v.w);
        int off = cc*2048 + SWZ(o, (j>>1)) + (j&1)*8;
        *(uint2*)(sm + WH_OFF + off) = make_uint2(h0u, h1u);
    }

    // ---- per-pixel harmonics (pixel: row h0+warp, col w0+lane) ----
    float th = theta[((size_t)n*HH + (h0 + warp))*WW + (w0 + lane)];
    float s1, c1;
    sincosf(6.28318530717958647692f * th, &s1, &c1);
    const float c2 = 2.f*c1*c1 - 1.f, s2 = 2.f*s1*c1;
    const float cps = c1 + s1, cms = c1 - s1;
    const int ctr = XROW + (lane + 4);           // r3=1 row, this lane's column
    const float Q = 0.35355339059327376220f;     // 1/(2*sqrt(2))

    // ---- per-lane ldmatrix addresses (unchanged layouts) ----
    uint32_t aswz0 = SWZ(warp*32 +      (lane & 15), (lane >> 4));
    uint32_t aswz1 = SWZ(warp*32 + 16 + (lane & 15), (lane >> 4));
    const int olc = (lane & 7) + ((lane >> 4) << 3);
    const int whalf = (lane >> 3) & 1;
    uint32_t wswz[4];
    #pragma unroll
    for (int np = 0; np < 4; np++) wswz[np] = SWZ(np*16 + olc, whalf);

    float acc[2][8][4];
    #pragma unroll
    for (int a = 0; a < 2; a++)
        #pragma unroll
        for (int b = 0; b < 8; b++)
            #pragma unroll
            for (int q = 0; q < 4; q++) acc[a][b][q] = 0.f;

    __syncthreads();         // W tiles visible to all warps; ONLY CTA barrier in the kernel

    int xbuf = 0;            // c % 3
    for (int c = 0; c < NCHUNK; c++){
        // warp-local X(c) readiness
        if (c < NCHUNK-1) asm volatile("cp.async.wait_group 1;" ::: "memory");
        else              asm volatile("cp.async.wait_group 0;" ::: "memory");

        // prefetch X(c+2) into buf (c+2)%3 (never the buf being read)
        if (c + 2 < NCHUNK){
            int wb = xbuf + 2; if (wb >= 3) wb -= 3;
            load_chunk_warp(xb, c+2, wb, xwbase, lane, soff);
        }

        // ---- build A(c): 4 channels x 4 harmonics for this lane's pixel ----
        {
            const float* xc = smf + (warp*(XW_WARP_BYTES/4)) + xbuf*(XBUF_BYTES/4);
            uint32_t hu[8];
            #pragma unroll
            for (int jj = 0; jj < 4; jj++){
                const float* xp = xc + jj*120 + ctr;
                float t0=xp[-XROW-1], t1=xp[-XROW], t2=xp[-XROW+1];
                float t3=xp[-1],      t4=xp[0],     t5=xp[1];
                float t6=xp[XROW-1],  t7=xp[XROW],  t8=xp[XROW+1];
                float ring = ((t0+t1)+(t2+t3)) + ((t5+t6)+(t7+t8));
                float z2 = Q*(cps*(t8-t0) + cms*(t2-t6)) + 0.5f*(c1*(t5-t3) + s1*(t7-t1));
                float z3 = 0.5f*(s2*((t0+t8)-(t2+t6)) + c2*((t3+t5)-(t1+t7)));
                hu[jj*2]   = pf16(t4, Q*ring);
                hu[jj*2+1] = pf16(z2, z3);
            }
            char* ah = sm + AH_OFF + (c & 1)*8192;
            *(uint4*)(ah + SWZ(tid,0)) = make_uint4(hu[0],hu[1],hu[2],hu[3]);
            *(uint4*)(ah + SWZ(tid,1)) = make_uint4(hu[4],hu[5],hu[6],hu[7]);
        }
        __syncwarp();        // A rows warp-private: STS -> ldmatrix visibility only

        // ---- tensor-core GEMM: one k16 block ----
        {
            const unsigned abuf = sb + AH_OFF + (unsigned)(c & 1)*8192u;
            uint32_t ahf[2][4];
            ldm4(ahf[0], abuf + aswz0);
            ldm4(ahf[1], abuf + aswz1);
            uint32_t wh_base = sb + WH_OFF + (unsigned)c*2048u;
            #pragma unroll
            for (int np = 0; np < 4; np++){
                uint32_t bh[4];
                ldm4(bh, wh_base + wswz[np]);
                #pragma unroll
                for (int s = 0; s < 2; s++){
                    #pragma unroll
                    for (int mt = 0; mt < 2; mt++)
                        mma16816(acc[mt][np*2 + s], ahf[mt], bh[s*2], bh[s*2+1]);
                }
            }
        }
        if (++xbuf == 3) xbuf = 0;
    }

    // ---- epilogue: bias + store ----
    const int gr = lane >> 2, tg = lane & 3;
    float* ob = out + (size_t)n*CO*HH*WW;
    #pragma unroll
    for (int mt = 0; mt < 2; mt++){
        size_t off0 = (size_t)(h0 + warp)*WW + (w0 + mt*16 + gr);
        size_t off1 = off0 + 8;
        #pragma unroll
        for (int nt = 0; nt < 8; nt++){
            int o = nt*8 + tg*2;
            float b0v = __ldg(bias + o);
            float b1v = __ldg(bias + o + 1);
            ob[(size_t)o*(HH*WW)     + off0] = acc[mt][nt][0] + b0v;
            ob[(size_t)(o+1)*(HH*WW) + off0] = acc[mt][nt][1] + b1v;
            ob[(size_t)o*(HH*WW)     + off1] = acc[mt][nt][2] + b0v;
            ob[(size_t)(o+1)*(HH*WW) + off1] = acc[mt][nt][3] + b1v;
        }
    }
}

extern "C" void kernel_launch(void* const* d_in, const int* in_sizes, int n_in,
                              void* d_out, int out_size) {
    const float* x     = (const float*)d_in[0];
    const float* theta = (const float*)d_in[1];
    const float* wts   = (const float*)d_in[2];
    const float* bias  = (const float*)d_in[3];
    float* out = (float*)d_out;

    cudaFuncSetAttribute(steered_mma,
                         cudaFuncAttributeMaxDynamicSharedMemorySize, SMEM_BYTES);
    dim3 grid(WW/TW, HH/TH, NB);
    steered_mma<<<grid, NTHREADS, SMEM_BYTES>>>(x, theta, wts, bias, out);
}